// round 2
// baseline (speedup 1.0000x reference)
#include <cuda_runtime.h>

#define BATCH   4
#define SEQ     4096
#define DMODEL  1024
#define HEAD    64
#define BT      (BATCH * SEQ)

typedef unsigned long long u64;

// ---- f32x2 packed helpers (sm_103a full-rate fp32 path) ----
__device__ __forceinline__ u64 pack2(float lo, float hi) {
    u64 r; asm("mov.b64 %0, {%1, %2};" : "=l"(r) : "f"(lo), "f"(hi)); return r;
}
__device__ __forceinline__ void unpack2(u64 v, float& lo, float& hi) {
    asm("mov.b64 {%0, %1}, %2;" : "=f"(lo), "=f"(hi) : "l"(v));
}
__device__ __forceinline__ void fma2(u64& d, u64 a, u64 b) {
    asm("fma.rn.f32x2 %0, %1, %2, %0;" : "+l"(d) : "l"(a), "l"(b));
}
__device__ __forceinline__ u64 mul2(u64 a, u64 b) {
    u64 d; asm("mul.rn.f32x2 %0, %1, %2;" : "=l"(d) : "l"(a), "l"(b)); return d;
}

// Scratch (allocation-free rule: __device__ globals)
__device__ float g_q[BT * HEAD];
__device__ float g_k[BT * HEAD];
__device__ float g_v[BT * HEAD];

// ---------------------------------------------------------------------------
// Projection GEMM: out = x @ W + b. Tile BM=64, BN=64, BK=32, 256 thr, 4x4.
// f32x2 pairing along K; all smem traffic via LDS.128/STS.128, conflict-free.
// ---------------------------------------------------------------------------
__global__ __launch_bounds__(256) void proj_kernel(
    const float* __restrict__ x,
    const float* __restrict__ Wq, const float* __restrict__ bq,
    const float* __restrict__ Wk, const float* __restrict__ bk,
    const float* __restrict__ Wv, const float* __restrict__ bv)
{
    const int sel = blockIdx.y;
    const float* __restrict__ W    = (sel == 0) ? Wq : (sel == 1) ? Wk : Wv;
    const float* __restrict__ bias = (sel == 0) ? bq : (sel == 1) ? bk : bv;
    float* __restrict__ out        = (sel == 0) ? g_q : (sel == 1) ? g_k : g_v;

    __shared__ float Xs[64 * 32];   // [m][k], stride 32
    __shared__ float Ws[32 * 64];   // [k][n], stride 64

    const int t  = threadIdx.x;
    const int tx = t & 15;
    const int ty = t >> 4;
    const int m0 = blockIdx.x * 64;

    u64 acc[4][4] = {};   // pairs over (k even, k odd)

    for (int k0 = 0; k0 < DMODEL; k0 += 32) {
        // X tile 64x32 as 512 float4
        #pragma unroll
        for (int i = t; i < 512; i += 256) {
            int r = i >> 3, c = i & 7;
            ((float4*)Xs)[i] = *(const float4*)&x[(size_t)(m0 + r) * DMODEL + k0 + c * 4];
        }
        // W tile 32x64 as 512 float4
        #pragma unroll
        for (int i = t; i < 512; i += 256) {
            int k = i >> 4, c = i & 15;
            ((float4*)Ws)[i] = *(const float4*)&W[(size_t)(k0 + k) * HEAD + c * 4];
        }
        __syncthreads();

        #pragma unroll
        for (int k4 = 0; k4 < 8; k4++) {
            ulonglong2 xq[4];
            #pragma unroll
            for (int i = 0; i < 4; i++)
                xq[i] = *(const ulonglong2*)&Xs[(ty * 4 + i) * 32 + k4 * 4];
            float4 wk0 = *(const float4*)&Ws[(k4 * 4 + 0) * 64 + tx * 4];
            float4 wk1 = *(const float4*)&Ws[(k4 * 4 + 1) * 64 + tx * 4];
            float4 wk2 = *(const float4*)&Ws[(k4 * 4 + 2) * 64 + tx * 4];
            float4 wk3 = *(const float4*)&Ws[(k4 * 4 + 3) * 64 + tx * 4];
            u64 wv0[4], wv1[4];
            wv0[0] = pack2(wk0.x, wk1.x); wv0[1] = pack2(wk0.y, wk1.y);
            wv0[2] = pack2(wk0.z, wk1.z); wv0[3] = pack2(wk0.w, wk1.w);
            wv1[0] = pack2(wk2.x, wk3.x); wv1[1] = pack2(wk2.y, wk3.y);
            wv1[2] = pack2(wk2.z, wk3.z); wv1[3] = pack2(wk2.w, wk3.w);
            #pragma unroll
            for (int i = 0; i < 4; i++)
                #pragma unroll
                for (int j = 0; j < 4; j++) {
                    fma2(acc[i][j], xq[i].x, wv0[j]);
                    fma2(acc[i][j], xq[i].y, wv1[j]);
                }
        }
        __syncthreads();
    }

    #pragma unroll
    for (int i = 0; i < 4; i++) {
        int r = m0 + ty * 4 + i;
        float4 res;
        float lo, hi;
        unpack2(acc[i][0], lo, hi); res.x = lo + hi + bias[tx * 4 + 0];
        unpack2(acc[i][1], lo, hi); res.y = lo + hi + bias[tx * 4 + 1];
        unpack2(acc[i][2], lo, hi); res.z = lo + hi + bias[tx * 4 + 2];
        unpack2(acc[i][3], lo, hi); res.w = lo + hi + bias[tx * 4 + 3];
        *(float4*)&out[(size_t)r * HEAD + tx * 4] = res;
    }
}

// ---------------------------------------------------------------------------
// Flash attention fp32, online softmax. Br=Bc=64, D=64, 256 threads, 4x4.
// All smem stride 64 (row 256B), LDS.128 everywhere (broadcast / contiguous
// 16B-chunk patterns -> conflict-free). f32x2 pairing along reduction axes.
// Grid 1-D, heavy tiles first: g -> (mt = 63 - g/4, b = g%4).
// ---------------------------------------------------------------------------
#define SMEM_ATTN (3 * 64 * 64 * sizeof(float))   // 49152 B

__global__ __launch_bounds__(256) void attn_kernel(float* __restrict__ out)
{
    extern __shared__ float sm[];
    float* Qs = sm;            // [64][64]
    float* Ks = sm + 4096;     // [64][64], reused as P
    float* Vs = sm + 8192;     // [64][64]

    const int g  = blockIdx.x;
    const int mt = 63 - (g >> 2);   // heavy (long) tiles first, all batches
    const int b  = g & 3;
    const int row0 = mt * 64;

    const int t  = threadIdx.x;
    const int tx = t & 15;
    const int ty = t >> 4;

    // Q tile once (float4, coalesced, direct copy: layouts match)
    {
        const float4* qg = (const float4*)(g_q + ((size_t)b * SEQ + row0) * HEAD);
        #pragma unroll
        for (int i = t; i < 1024; i += 256) ((float4*)Qs)[i] = qg[i];
    }

    float m_i[4], l_i[4];
    u64 o2[4][4] = {};   // pairs over (j even, j odd)
    #pragma unroll
    for (int i = 0; i < 4; i++) { m_i[i] = -1e30f; l_i[i] = 0.0f; }

    const float scale = 1.0f / 32.0f;   // 1/sqrt(1024)

    for (int kt = 0; kt <= mt; kt++) {
        __syncthreads();   // previous P / V fully consumed
        const float4* kg = (const float4*)(g_k + ((size_t)b * SEQ + kt * 64) * HEAD);
        const float4* vg = (const float4*)(g_v + ((size_t)b * SEQ + kt * 64) * HEAD);
        #pragma unroll
        for (int i = t; i < 1024; i += 256) {
            ((float4*)Ks)[i] = kg[i];
            ((float4*)Vs)[i] = vg[i];
        }
        __syncthreads();

        // ---- S = Q K^T, pairs over d ----
        u64 acc[4][4] = {};
        #pragma unroll 4
        for (int d4 = 0; d4 < 16; d4++) {
            ulonglong2 q2[4], k2[4];
            #pragma unroll
            for (int i = 0; i < 4; i++)
                q2[i] = *(const ulonglong2*)&Qs[(ty * 4 + i) * 64 + d4 * 4];
            #pragma unroll
            for (int j = 0; j < 4; j++)
                k2[j] = *(const ulonglong2*)&Ks[(tx * 4 + j) * 64 + d4 * 4];
            #pragma unroll
            for (int i = 0; i < 4; i++)
                #pragma unroll
                for (int j = 0; j < 4; j++) {
                    fma2(acc[i][j], q2[i].x, k2[j].x);
                    fma2(acc[i][j], q2[i].y, k2[j].y);
                }
        }
        float s[4][4];
        #pragma unroll
        for (int i = 0; i < 4; i++)
            #pragma unroll
            for (int j = 0; j < 4; j++) {
                float lo, hi; unpack2(acc[i][j], lo, hi);
                s[i][j] = (lo + hi) * scale;
            }

        if (kt == mt) {   // causal mask on diagonal tile
            #pragma unroll
            for (int i = 0; i < 4; i++)
                #pragma unroll
                for (int j = 0; j < 4; j++)
                    if (tx * 4 + j > ty * 4 + i) s[i][j] = -1e30f;
        }

        // ---- online softmax ----
        float p[4][4], alpha[4];
        #pragma unroll
        for (int i = 0; i < 4; i++) {
            float m = fmaxf(fmaxf(s[i][0], s[i][1]), fmaxf(s[i][2], s[i][3]));
            #pragma unroll
            for (int off = 8; off > 0; off >>= 1)
                m = fmaxf(m, __shfl_xor_sync(0xffffffffu, m, off, 16));
            float m_new = fmaxf(m_i[i], m);
            alpha[i] = __expf(m_i[i] - m_new);
            m_i[i] = m_new;
            float r = 0.0f;
            #pragma unroll
            for (int j = 0; j < 4; j++) { p[i][j] = __expf(s[i][j] - m_new); r += p[i][j]; }
            #pragma unroll
            for (int off = 8; off > 0; off >>= 1)
                r += __shfl_xor_sync(0xffffffffu, r, off, 16);
            l_i[i] = l_i[i] * alpha[i] + r;
        }
        #pragma unroll
        for (int i = 0; i < 4; i++) {
            u64 a2 = pack2(alpha[i], alpha[i]);
            #pragma unroll
            for (int dd = 0; dd < 4; dd++) o2[i][dd] = mul2(o2[i][dd], a2);
        }

        // ---- P into K buffer (S reads of Ks are done) ----
        __syncthreads();
        #pragma unroll
        for (int i = 0; i < 4; i++) {
            float4 pr = make_float4(p[i][0], p[i][1], p[i][2], p[i][3]);
            *(float4*)&Ks[(ty * 4 + i) * 64 + tx * 4] = pr;
        }
        __syncthreads();

        // ---- O += P V, pairs over j ----
        #pragma unroll 4
        for (int j4 = 0; j4 < 16; j4++) {
            ulonglong2 pv2[4];
            #pragma unroll
            for (int i = 0; i < 4; i++)
                pv2[i] = *(const ulonglong2*)&Ks[(ty * 4 + i) * 64 + j4 * 4];
            float4 vj0 = *(const float4*)&Vs[(j4 * 4 + 0) * 64 + tx * 4];
            float4 vj1 = *(const float4*)&Vs[(j4 * 4 + 1) * 64 + tx * 4];
            float4 vj2 = *(const float4*)&Vs[(j4 * 4 + 2) * 64 + tx * 4];
            float4 vj3 = *(const float4*)&Vs[(j4 * 4 + 3) * 64 + tx * 4];
            u64 vv0[4], vv1[4];
            vv0[0] = pack2(vj0.x, vj1.x); vv0[1] = pack2(vj0.y, vj1.y);
            vv0[2] = pack2(vj0.z, vj1.z); vv0[3] = pack2(vj0.w, vj1.w);
            vv1[0] = pack2(vj2.x, vj3.x); vv1[1] = pack2(vj2.y, vj3.y);
            vv1[2] = pack2(vj2.z, vj3.z); vv1[3] = pack2(vj2.w, vj3.w);
            #pragma unroll
            for (int i = 0; i < 4; i++)
                #pragma unroll
                for (int dd = 0; dd < 4; dd++) {
                    fma2(o2[i][dd], pv2[i].x, vv0[dd]);
                    fma2(o2[i][dd], pv2[i].y, vv1[dd]);
                }
        }
    }

    // Epilogue: normalize + store
    #pragma unroll
    for (int i = 0; i < 4; i++) {
        float inv_l = 1.0f / l_i[i];
        int r = row0 + ty * 4 + i;
        float4 res; float lo, hi;
        unpack2(o2[i][0], lo, hi); res.x = (lo + hi) * inv_l;
        unpack2(o2[i][1], lo, hi); res.y = (lo + hi) * inv_l;
        unpack2(o2[i][2], lo, hi); res.z = (lo + hi) * inv_l;
        unpack2(o2[i][3], lo, hi); res.w = (lo + hi) * inv_l;
        *(float4*)&out[((size_t)b * SEQ + r) * HEAD + tx * 4] = res;
    }
}

// ---------------------------------------------------------------------------
extern "C" void kernel_launch(void* const* d_in, const int* in_sizes, int n_in,
                              void* d_out, int out_size)
{
    const float* x  = (const float*)d_in[0];
    const float* Wq = (const float*)d_in[1];
    const float* bq = (const float*)d_in[2];
    const float* Wk = (const float*)d_in[3];
    const float* bk = (const float*)d_in[4];
    const float* Wv = (const float*)d_in[5];
    const float* bv = (const float*)d_in[6];
    float* out = (float*)d_out;
    (void)in_sizes; (void)n_in; (void)out_size;

    proj_kernel<<<dim3(BT / 64, 3), 256>>>(x, Wq, bq, Wk, bk, Wv, bv);

    cudaFuncSetAttribute(attn_kernel, cudaFuncAttributeMaxDynamicSharedMemorySize,
                         (int)SMEM_ATTN);
    attn_kernel<<<SEQ / 64 * BATCH, 256, SMEM_ATTN>>>(out);
}

// round 4
// speedup vs baseline: 4.7147x; 4.7147x over previous
#include <cuda_runtime.h>

#define BATCH   4
#define SEQ     4096
#define DMODEL  1024
#define HEAD    64
#define BT      (BATCH * SEQ)

typedef unsigned int u32;
typedef unsigned short u16;

// Scratch for projected q, k, v
__device__ float g_q[BT * HEAD];
__device__ float g_k[BT * HEAD];
__device__ float g_v[BT * HEAD];

// ============================ helpers ============================
__device__ __forceinline__ u32 smem_u32(const void* p) {
    u32 a;
    asm("{ .reg .u64 t; cvta.to.shared.u64 t, %1; cvt.u32.u64 %0, t; }" : "=r"(a) : "l"(p));
    return a;
}
__device__ __forceinline__ u32 sw128(u32 off) { return off ^ ((off >> 3) & 0x70); }

// ldmatrix x4 (non-transposed / transposed)
__device__ __forceinline__ void ldsm4(u32 a, u32& r0, u32& r1, u32& r2, u32& r3) {
    asm volatile("ldmatrix.sync.aligned.m8n8.x4.shared.b16 {%0,%1,%2,%3}, [%4];"
                 : "=r"(r0), "=r"(r1), "=r"(r2), "=r"(r3) : "r"(a));
}
__device__ __forceinline__ void ldsm4t(u32 a, u32& r0, u32& r1, u32& r2, u32& r3) {
    asm volatile("ldmatrix.sync.aligned.m8n8.x4.trans.shared.b16 {%0,%1,%2,%3}, [%4];"
                 : "=r"(r0), "=r"(r1), "=r"(r2), "=r"(r3) : "r"(a));
}

// bf16 mma m16n8k16, fp32 accumulate
__device__ __forceinline__ void mma16816(float* d, u32 a0, u32 a1, u32 a2, u32 a3,
                                         u32 b0, u32 b1) {
    asm volatile(
        "mma.sync.aligned.m16n8k16.row.col.f32.bf16.bf16.f32 "
        "{%0,%1,%2,%3},{%4,%5,%6,%7},{%8,%9},{%0,%1,%2,%3};"
        : "+f"(d[0]), "+f"(d[1]), "+f"(d[2]), "+f"(d[3])
        : "r"(a0), "r"(a1), "r"(a2), "r"(a3), "r"(b0), "r"(b1));
}

// pack pair (a=low element, b=high element) into bf16x2 hi + compensated lo
__device__ __forceinline__ void pack_hilo(float a, float b, u32& h, u32& l) {
    asm("cvt.rn.bf16x2.f32 %0, %1, %2;" : "=r"(h) : "f"(b), "f"(a));
    float ra = __uint_as_float(h << 16);
    float rb = __uint_as_float(h & 0xFFFF0000u);
    asm("cvt.rn.bf16x2.f32 %0, %1, %2;" : "=r"(l) : "f"(b - rb), "f"(a - ra));
}

// ldmatrix fragment address: tile base (byte addr), row0, byte col base.
// Tiles: (r0..+7, c), (r0+8..+15, c), (r0..+7, c+16), (r0+8..+15, c+16)
// Rows are 128 bytes, SW128-swizzled.
__device__ __forceinline__ u32 frag_addr(u32 base, int row0, int colb) {
    int lane = threadIdx.x & 31;
    int tile = lane >> 3, l7 = lane & 7;
    int row = row0 + l7 + ((tile & 1) << 3);
    int col = colb + ((tile >> 1) << 4);
    return base + sw128((u32)(row * 128 + col));
}

// ============================ Projection kernel ============================
// CTA: 128 rows of x, all 192 output cols (q|k|v). K chunks of 64.
// smem: XH/XL [128][64]bf16, WH/WL [192][64]bf16 (n-major).
#define PJ_XH 0
#define PJ_XL 16384
#define PJ_WH 32768
#define PJ_WL (32768 + 24576)
#define PJ_SMEM (PJ_WL + 24576)   // 81920

__global__ __launch_bounds__(256) void proj_kernel(
    const float* __restrict__ x,
    const float* __restrict__ Wq, const float* __restrict__ bq,
    const float* __restrict__ Wk, const float* __restrict__ bk,
    const float* __restrict__ Wv, const float* __restrict__ bv)
{
    extern __shared__ char sm[];
    const u32 smb = smem_u32(sm);
    const int t = threadIdx.x, w = t >> 5, lane = t & 31;
    const int g = lane >> 2, tg = lane & 3;
    const int m0 = blockIdx.x * 128;
    const int mb = 16 * w;

    const float* Ws[3] = { Wq, Wk, Wv };
    const float* Bs[3] = { bq, bk, bv };
    float* Os[3] = { g_q, g_k, g_v };

    float acc[24][4];
    #pragma unroll
    for (int i = 0; i < 24; i++)
        #pragma unroll
        for (int e = 0; e < 4; e++) acc[i][e] = 0.0f;

    for (int c = 0; c < 16; c++) {
        const int k0 = c * 64;
        if (c) __syncthreads();   // prior ldmatrix done before overwrite

        // X chunk [128m x 64k] fp32 -> bf16 hi/lo
        #pragma unroll
        for (int j = 0; j < 8; j++) {
            int idx = t + j * 256;
            int r = idx >> 4, cq = idx & 15;
            float4 v = *(const float4*)&x[(size_t)(m0 + r) * DMODEL + k0 + cq * 4];
            uint2 h, l;
            pack_hilo(v.x, v.y, h.x, l.x);
            pack_hilo(v.z, v.w, h.y, l.y);
            u32 off = sw128((u32)(r * 128 + cq * 8));
            *(uint2*)(sm + PJ_XH + off) = h;
            *(uint2*)(sm + PJ_XL + off) = l;
        }
        // W chunk: 3 sels, [64k x 64n] gmem -> n-major smem [n][k]
        #pragma unroll
        for (int j = 0; j < 12; j++) {
            int idx = t + j * 256;
            int sel = idx >> 10, rem = idx & 1023;
            int nl = rem & 63, kq = rem >> 6;          // 4 consecutive k
            const float* Wp = Ws[sel];
            float w0 = Wp[(size_t)(k0 + kq * 4 + 0) * HEAD + nl];
            float w1 = Wp[(size_t)(k0 + kq * 4 + 1) * HEAD + nl];
            float w2 = Wp[(size_t)(k0 + kq * 4 + 2) * HEAD + nl];
            float w3 = Wp[(size_t)(k0 + kq * 4 + 3) * HEAD + nl];
            uint2 h, l;
            pack_hilo(w0, w1, h.x, l.x);
            pack_hilo(w2, w3, h.y, l.y);
            u32 off = sw128((u32)((sel * 64 + nl) * 128 + kq * 8));
            *(uint2*)(sm + PJ_WH + off) = h;
            *(uint2*)(sm + PJ_WL + off) = l;
        }
        __syncthreads();

        // A fragments for this chunk (4 ksteps)
        u32 aH[4][4], aL[4][4];
        #pragma unroll
        for (int kk = 0; kk < 4; kk++) {
            ldsm4(frag_addr(smb + PJ_XH, mb, kk * 32), aH[kk][0], aH[kk][1], aH[kk][2], aH[kk][3]);
            ldsm4(frag_addr(smb + PJ_XL, mb, kk * 32), aL[kk][0], aL[kk][1], aL[kk][2], aL[kk][3]);
        }
        #pragma unroll
        for (int nb = 0; nb < 12; nb++) {
            #pragma unroll
            for (int kk = 0; kk < 4; kk++) {
                u32 bh0, bh1, bh2, bh3, bl0, bl1, bl2, bl3;
                ldsm4(frag_addr(smb + PJ_WH, nb * 16, kk * 32), bh0, bh1, bh2, bh3);
                ldsm4(frag_addr(smb + PJ_WL, nb * 16, kk * 32), bl0, bl1, bl2, bl3);
                // non-trans pairing: nfrag0 = {r0,r2}, nfrag1 = {r1,r3}
                mma16816(acc[2*nb],   aH[kk][0], aH[kk][1], aH[kk][2], aH[kk][3], bh0, bh2);
                mma16816(acc[2*nb],   aH[kk][0], aH[kk][1], aH[kk][2], aH[kk][3], bl0, bl2);
                mma16816(acc[2*nb],   aL[kk][0], aL[kk][1], aL[kk][2], aL[kk][3], bh0, bh2);
                mma16816(acc[2*nb+1], aH[kk][0], aH[kk][1], aH[kk][2], aH[kk][3], bh1, bh3);
                mma16816(acc[2*nb+1], aH[kk][0], aH[kk][1], aH[kk][2], aH[kk][3], bl1, bl3);
                mma16816(acc[2*nb+1], aL[kk][0], aL[kk][1], aL[kk][2], aL[kk][3], bh1, bh3);
            }
        }
    }

    // epilogue: bias + store
    #pragma unroll
    for (int nf = 0; nf < 24; nf++) {
        int n = nf * 8 + 2 * tg;
        int sel = n >> 6, nl = n & 63;
        float b0 = Bs[sel][nl], b1 = Bs[sel][nl + 1];
        int r0 = m0 + mb + g;
        float2 v0 = make_float2(acc[nf][0] + b0, acc[nf][1] + b1);
        float2 v1 = make_float2(acc[nf][2] + b0, acc[nf][3] + b1);
        *(float2*)&Os[sel][(size_t)r0 * HEAD + nl] = v0;
        *(float2*)&Os[sel][(size_t)(r0 + 8) * HEAD + nl] = v1;
    }
}

// ============================ Attention kernel ============================
// CTA = (b, mt): 128 query rows, k-tiles of 128. Warp = 16 rows x full width.
// No-max softmax; O accumulates raw fp32 in regs; normalize once at end.
#define AT_QH 0
#define AT_QL 16384
#define AT_KH 32768
#define AT_KL 49152
#define AT_VH 65536
#define AT_VL 81920
#define AT_SMEM 98304

__global__ __launch_bounds__(256) void attn_kernel(float* __restrict__ out)
{
    extern __shared__ char sm[];
    const u32 smb = smem_u32(sm);
    const int t = threadIdx.x, w = t >> 5, lane = t & 31;
    const int g = lane >> 2, tg = lane & 3;
    const int gb = blockIdx.x;
    const int mt = 31 - (gb >> 2);     // heavy tiles first
    const int b  = gb & 3;
    const int row0 = mt * 128;
    const int mb = 16 * w;
    const float scale = 1.0f / 32.0f;  // 1/sqrt(1024)

    // Q tile -> smem bf16 hi/lo
    {
        const float* qg = g_q + ((size_t)b * SEQ + row0) * HEAD;
        #pragma unroll
        for (int j = 0; j < 8; j++) {
            int idx = t + j * 256;
            int r = idx >> 4, cq = idx & 15;
            float4 v = *(const float4*)&qg[(size_t)r * HEAD + cq * 4];
            uint2 h, l;
            pack_hilo(v.x, v.y, h.x, l.x);
            pack_hilo(v.z, v.w, h.y, l.y);
            u32 off = sw128((u32)(r * 128 + cq * 8));
            *(uint2*)(sm + AT_QH + off) = h;
            *(uint2*)(sm + AT_QL + off) = l;
        }
    }
    __syncthreads();

    // Q fragments (loop-invariant)
    u32 qH[4][4], qL[4][4];
    #pragma unroll
    for (int kk = 0; kk < 4; kk++) {
        ldsm4(frag_addr(smb + AT_QH, mb, kk * 32), qH[kk][0], qH[kk][1], qH[kk][2], qH[kk][3]);
        ldsm4(frag_addr(smb + AT_QL, mb, kk * 32), qL[kk][0], qL[kk][1], qL[kk][2], qL[kk][3]);
    }

    float oacc[8][4];
    #pragma unroll
    for (int i = 0; i < 8; i++)
        #pragma unroll
        for (int e = 0; e < 4; e++) oacc[i][e] = 0.0f;
    float l0 = 0.0f, l1 = 0.0f;
    const int rowg0 = row0 + mb + g, rowg1 = rowg0 + 8;

    for (int kt = 0; kt <= mt; kt++) {
        __syncthreads();   // prior V ldmatrix done before overwrite
        // K, V tiles -> smem bf16 hi/lo (both [128 rows][64 cols], no transpose)
        const float* kg = g_k + ((size_t)b * SEQ + kt * 128) * HEAD;
        const float* vg = g_v + ((size_t)b * SEQ + kt * 128) * HEAD;
        #pragma unroll
        for (int j = 0; j < 8; j++) {
            int idx = t + j * 256;
            int r = idx >> 4, cq = idx & 15;
            u32 off = sw128((u32)(r * 128 + cq * 8));
            float4 v = *(const float4*)&kg[(size_t)r * HEAD + cq * 4];
            uint2 h, l;
            pack_hilo(v.x, v.y, h.x, l.x);
            pack_hilo(v.z, v.w, h.y, l.y);
            *(uint2*)(sm + AT_KH + off) = h;
            *(uint2*)(sm + AT_KL + off) = l;
            float4 u = *(const float4*)&vg[(size_t)r * HEAD + cq * 4];
            pack_hilo(u.x, u.y, h.x, l.x);
            pack_hilo(u.z, u.w, h.y, l.y);
            *(uint2*)(sm + AT_VH + off) = h;
            *(uint2*)(sm + AT_VL + off) = l;
        }
        __syncthreads();

        // ---- S = Q K^T (hi*hi + hi*lo + lo*hi) ----
        float sacc[16][4];
        #pragma unroll
        for (int i = 0; i < 16; i++)
            #pragma unroll
            for (int e = 0; e < 4; e++) sacc[i][e] = 0.0f;

        #pragma unroll
        for (int nb = 0; nb < 8; nb++) {
            #pragma unroll
            for (int kk = 0; kk < 4; kk++) {
                u32 bh0, bh1, bh2, bh3, bl0, bl1, bl2, bl3;
                ldsm4(frag_addr(smb + AT_KH, nb * 16, kk * 32), bh0, bh1, bh2, bh3);
                ldsm4(frag_addr(smb + AT_KL, nb * 16, kk * 32), bl0, bl1, bl2, bl3);
                mma16816(sacc[2*nb],   qH[kk][0], qH[kk][1], qH[kk][2], qH[kk][3], bh0, bh2);
                mma16816(sacc[2*nb],   qH[kk][0], qH[kk][1], qH[kk][2], qH[kk][3], bl0, bl2);
                mma16816(sacc[2*nb],   qL[kk][0], qL[kk][1], qL[kk][2], qL[kk][3], bh0, bh2);
                mma16816(sacc[2*nb+1], qH[kk][0], qH[kk][1], qH[kk][2], qH[kk][3], bh1, bh3);
                mma16816(sacc[2*nb+1], qH[kk][0], qH[kk][1], qH[kk][2], qH[kk][3], bl1, bl3);
                mma16816(sacc[2*nb+1], qL[kk][0], qL[kk][1], qL[kk][2], qL[kk][3], bh1, bh3);
            }
        }

        // ---- masked exp (no max), row-sum accumulation ----
        #pragma unroll
        for (int nf = 0; nf < 16; nf++) {
            int colb = kt * 128 + nf * 8 + 2 * tg;
            float p0 = (colb     <= rowg0) ? __expf(sacc[nf][0] * scale) : 0.0f;
            float p1 = (colb + 1 <= rowg0) ? __expf(sacc[nf][1] * scale) : 0.0f;
            float p2 = (colb     <= rowg1) ? __expf(sacc[nf][2] * scale) : 0.0f;
            float p3 = (colb + 1 <= rowg1) ? __expf(sacc[nf][3] * scale) : 0.0f;
            l0 += p0 + p1; l1 += p2 + p3;
            sacc[nf][0] = p0; sacc[nf][1] = p1; sacc[nf][2] = p2; sacc[nf][3] = p3;
        }

        // ---- O += P V (P in regs; V via ldmatrix.trans) ----
        #pragma unroll
        for (int kk = 0; kk < 8; kk++) {
            u32 ah[4], al[4];
            pack_hilo(sacc[2*kk][0],   sacc[2*kk][1],   ah[0], al[0]);
            pack_hilo(sacc[2*kk][2],   sacc[2*kk][3],   ah[1], al[1]);
            pack_hilo(sacc[2*kk+1][0], sacc[2*kk+1][1], ah[2], al[2]);
            pack_hilo(sacc[2*kk+1][2], sacc[2*kk+1][3], ah[3], al[3]);
            #pragma unroll
            for (int nb = 0; nb < 4; nb++) {
                u32 vh0, vh1, vh2, vh3, vl0, vl1, vl2, vl3;
                ldsm4t(frag_addr(smb + AT_VH, kk * 16, nb * 32), vh0, vh1, vh2, vh3);
                ldsm4t(frag_addr(smb + AT_VL, kk * 16, nb * 32), vl0, vl1, vl2, vl3);
                // trans pairing: nfrag0 = {r0,r1}, nfrag1 = {r2,r3}
                mma16816(oacc[2*nb],   ah[0], ah[1], ah[2], ah[3], vh0, vh1);
                mma16816(oacc[2*nb],   ah[0], ah[1], ah[2], ah[3], vl0, vl1);
                mma16816(oacc[2*nb],   al[0], al[1], al[2], al[3], vh0, vh1);
                mma16816(oacc[2*nb+1], ah[0], ah[1], ah[2], ah[3], vh2, vh3);
                mma16816(oacc[2*nb+1], ah[0], ah[1], ah[2], ah[3], vl2, vl3);
                mma16816(oacc[2*nb+1], al[0], al[1], al[2], al[3], vh2, vh3);
            }
        }
    }

    // ---- epilogue: reduce l across quad, normalize, store ----
    l0 += __shfl_xor_sync(0xffffffffu, l0, 1);
    l0 += __shfl_xor_sync(0xffffffffu, l0, 2);
    l1 += __shfl_xor_sync(0xffffffffu, l1, 1);
    l1 += __shfl_xor_sync(0xffffffffu, l1, 2);
    float inv0 = 1.0f / l0, inv1 = 1.0f / l1;

    #pragma unroll
    for (int nf = 0; nf < 8; nf++) {
        int col = nf * 8 + 2 * tg;
        float2 v0 = make_float2(oacc[nf][0] * inv0, oacc[nf][1] * inv0);
        float2 v1 = make_float2(oacc[nf][2] * inv1, oacc[nf][3] * inv1);
        *(float2*)&out[((size_t)b * SEQ + rowg0) * HEAD + col] = v0;
        *(float2*)&out[((size_t)b * SEQ + rowg1) * HEAD + col] = v1;
    }
}

// ============================ Launch ============================
extern "C" void kernel_launch(void* const* d_in, const int* in_sizes, int n_in,
                              void* d_out, int out_size)
{
    const float* x  = (const float*)d_in[0];
    const float* Wq = (const float*)d_in[1];
    const float* bq = (const float*)d_in[2];
    const float* Wk = (const float*)d_in[3];
    const float* bk = (const float*)d_in[4];
    const float* Wv = (const float*)d_in[5];
    const float* bv = (const float*)d_in[6];
    float* out = (float*)d_out;
    (void)in_sizes; (void)n_in; (void)out_size;

    cudaFuncSetAttribute(proj_kernel, cudaFuncAttributeMaxDynamicSharedMemorySize, PJ_SMEM);
    cudaFuncSetAttribute(attn_kernel, cudaFuncAttributeMaxDynamicSharedMemorySize, AT_SMEM);

    proj_kernel<<<BT / 128, 256, PJ_SMEM>>>(x, Wq, bq, Wk, bk, Wv, bv);
    attn_kernel<<<(SEQ / 128) * BATCH, 256, AT_SMEM>>>(out);
}

// round 5
// speedup vs baseline: 6.9397x; 1.4719x over previous
#include <cuda_runtime.h>

#define BATCH   4
#define SEQ     4096
#define DMODEL  1024
#define HEAD    64
#define BT      (BATCH * SEQ)
#define TILE_BYTES 16384   // one 128x64 bf16 plane tile, SW128 swizzled

typedef unsigned int u32;
typedef unsigned short u16;

// bf16 hi/lo operand planes, stored in attention-ready swizzled tile layout:
// plane[b*32 + tile][ sw128(rl*128 + c*2) ]
__device__ u16 g_qh[BT * HEAD];
__device__ u16 g_ql[BT * HEAD];
__device__ u16 g_kh[BT * HEAD];
__device__ u16 g_kl[BT * HEAD];
__device__ u16 g_vh[BT * HEAD];
__device__ u16 g_vl[BT * HEAD];
// split-K partials
__device__ float g_po[2][BT * HEAD];
__device__ float g_pl[2][BT];

// ============================ helpers ============================
__device__ __forceinline__ u32 smem_u32(const void* p) {
    u32 a;
    asm("{ .reg .u64 t; cvta.to.shared.u64 t, %1; cvt.u32.u64 %0, t; }" : "=r"(a) : "l"(p));
    return a;
}
__device__ __forceinline__ u32 sw128(u32 off) { return off ^ ((off >> 3) & 0x70); }

__device__ __forceinline__ void ldsm4(u32 a, u32& r0, u32& r1, u32& r2, u32& r3) {
    asm volatile("ldmatrix.sync.aligned.m8n8.x4.shared.b16 {%0,%1,%2,%3}, [%4];"
                 : "=r"(r0), "=r"(r1), "=r"(r2), "=r"(r3) : "r"(a));
}
__device__ __forceinline__ void ldsm4t(u32 a, u32& r0, u32& r1, u32& r2, u32& r3) {
    asm volatile("ldmatrix.sync.aligned.m8n8.x4.trans.shared.b16 {%0,%1,%2,%3}, [%4];"
                 : "=r"(r0), "=r"(r1), "=r"(r2), "=r"(r3) : "r"(a));
}
__device__ __forceinline__ void mma16816(float* d, u32 a0, u32 a1, u32 a2, u32 a3,
                                         u32 b0, u32 b1) {
    asm volatile(
        "mma.sync.aligned.m16n8k16.row.col.f32.bf16.bf16.f32 "
        "{%0,%1,%2,%3},{%4,%5,%6,%7},{%8,%9},{%0,%1,%2,%3};"
        : "+f"(d[0]), "+f"(d[1]), "+f"(d[2]), "+f"(d[3])
        : "r"(a0), "r"(a1), "r"(a2), "r"(a3), "r"(b0), "r"(b1));
}
__device__ __forceinline__ void pack_hilo(float a, float b, u32& h, u32& l) {
    asm("cvt.rn.bf16x2.f32 %0, %1, %2;" : "=r"(h) : "f"(b), "f"(a));
    float ra = __uint_as_float(h << 16);
    float rb = __uint_as_float(h & 0xFFFF0000u);
    asm("cvt.rn.bf16x2.f32 %0, %1, %2;" : "=r"(l) : "f"(b - rb), "f"(a - ra));
}
__device__ __forceinline__ u32 frag_addr(u32 base, int row0, int colb) {
    int lane = threadIdx.x & 31;
    int tile = lane >> 3, l7 = lane & 7;
    int row = row0 + l7 + ((tile & 1) << 3);
    int col = colb + ((tile >> 1) << 4);
    return base + sw128((u32)(row * 128 + col));
}
// cp.async
__device__ __forceinline__ void cpa16(u32 dst, const void* src) {
    asm volatile("cp.async.cg.shared.global [%0], [%1], 16;" :: "r"(dst), "l"(src));
}
__device__ __forceinline__ void cp_commit() {
    asm volatile("cp.async.commit_group;" ::: "memory");
}
__device__ __forceinline__ void copy_plane(u32 dst, const char* src, int t) {
    #pragma unroll
    for (int j = 0; j < 4; j++)
        cpa16(dst + (u32)(t * 16 + j * 4096), src + t * 16 + j * 4096);
}

// ============================ Projection kernel ============================
// CTA: 128 rows of x, all 192 output cols (q|k|v). K chunks of 64. 3-combo
// bf16 split GEMM. Epilogue writes hi/lo planes in swizzled tile layout.
#define PJ_XH 0
#define PJ_XL 16384
#define PJ_WH 32768
#define PJ_WL (32768 + 24576)
#define PJ_SMEM (PJ_WL + 24576)   // 81920

__global__ __launch_bounds__(256) void proj_kernel(
    const float* __restrict__ x,
    const float* __restrict__ Wq, const float* __restrict__ bq,
    const float* __restrict__ Wk, const float* __restrict__ bk,
    const float* __restrict__ Wv, const float* __restrict__ bv)
{
    extern __shared__ char sm[];
    const u32 smb = smem_u32(sm);
    const int t = threadIdx.x, w = t >> 5, lane = t & 31;
    const int g = lane >> 2, tg = lane & 3;
    const int m0 = blockIdx.x * 128;
    const int mb = 16 * w;

    const float* Ws[3] = { Wq, Wk, Wv };
    const float* Bs[3] = { bq, bk, bv };

    float acc[24][4];
    #pragma unroll
    for (int i = 0; i < 24; i++)
        #pragma unroll
        for (int e = 0; e < 4; e++) acc[i][e] = 0.0f;

    for (int c = 0; c < 16; c++) {
        const int k0 = c * 64;
        if (c) __syncthreads();

        #pragma unroll
        for (int j = 0; j < 8; j++) {
            int idx = t + j * 256;
            int r = idx >> 4, cq = idx & 15;
            float4 v = *(const float4*)&x[(size_t)(m0 + r) * DMODEL + k0 + cq * 4];
            uint2 h, l;
            pack_hilo(v.x, v.y, h.x, l.x);
            pack_hilo(v.z, v.w, h.y, l.y);
            u32 off = sw128((u32)(r * 128 + cq * 8));
            *(uint2*)(sm + PJ_XH + off) = h;
            *(uint2*)(sm + PJ_XL + off) = l;
        }
        #pragma unroll
        for (int j = 0; j < 12; j++) {
            int idx = t + j * 256;
            int sel = idx >> 10, rem = idx & 1023;
            int nl = rem & 63, kq = rem >> 6;
            const float* Wp = Ws[sel];
            float w0 = Wp[(size_t)(k0 + kq * 4 + 0) * HEAD + nl];
            float w1 = Wp[(size_t)(k0 + kq * 4 + 1) * HEAD + nl];
            float w2 = Wp[(size_t)(k0 + kq * 4 + 2) * HEAD + nl];
            float w3 = Wp[(size_t)(k0 + kq * 4 + 3) * HEAD + nl];
            uint2 h, l;
            pack_hilo(w0, w1, h.x, l.x);
            pack_hilo(w2, w3, h.y, l.y);
            u32 off = sw128((u32)((sel * 64 + nl) * 128 + kq * 8));
            *(uint2*)(sm + PJ_WH + off) = h;
            *(uint2*)(sm + PJ_WL + off) = l;
        }
        __syncthreads();

        u32 aH[4][4], aL[4][4];
        #pragma unroll
        for (int kk = 0; kk < 4; kk++) {
            ldsm4(frag_addr(smb + PJ_XH, mb, kk * 32), aH[kk][0], aH[kk][1], aH[kk][2], aH[kk][3]);
            ldsm4(frag_addr(smb + PJ_XL, mb, kk * 32), aL[kk][0], aL[kk][1], aL[kk][2], aL[kk][3]);
        }
        #pragma unroll
        for (int nb = 0; nb < 12; nb++) {
            #pragma unroll
            for (int kk = 0; kk < 4; kk++) {
                u32 bh0, bh1, bh2, bh3, bl0, bl1, bl2, bl3;
                ldsm4(frag_addr(smb + PJ_WH, nb * 16, kk * 32), bh0, bh1, bh2, bh3);
                ldsm4(frag_addr(smb + PJ_WL, nb * 16, kk * 32), bl0, bl1, bl2, bl3);
                mma16816(acc[2*nb],   aH[kk][0], aH[kk][1], aH[kk][2], aH[kk][3], bh0, bh2);
                mma16816(acc[2*nb],   aH[kk][0], aH[kk][1], aH[kk][2], aH[kk][3], bl0, bl2);
                mma16816(acc[2*nb],   aL[kk][0], aL[kk][1], aL[kk][2], aL[kk][3], bh0, bh2);
                mma16816(acc[2*nb+1], aH[kk][0], aH[kk][1], aH[kk][2], aH[kk][3], bh1, bh3);
                mma16816(acc[2*nb+1], aH[kk][0], aH[kk][1], aH[kk][2], aH[kk][3], bl1, bl3);
                mma16816(acc[2*nb+1], aL[kk][0], aL[kk][1], aL[kk][2], aL[kk][3], bh1, bh3);
            }
        }
    }

    // epilogue: bias, bf16 hi/lo split, write into swizzled tile planes
    const size_t pbase = (size_t)blockIdx.x * TILE_BYTES;
    char* ph[3] = { (char*)g_qh + pbase, (char*)g_kh + pbase, (char*)g_vh + pbase };
    char* pl[3] = { (char*)g_ql + pbase, (char*)g_kl + pbase, (char*)g_vl + pbase };
    const int rl0 = mb + g, rl1 = rl0 + 8;
    #pragma unroll
    for (int nf = 0; nf < 24; nf++) {
        int n = nf * 8 + 2 * tg;
        int sel = n >> 6, nl = n & 63;
        float b0 = Bs[sel][nl], b1 = Bs[sel][nl + 1];
        u32 h0, l0r, h1, l1r;
        pack_hilo(acc[nf][0] + b0, acc[nf][1] + b1, h0, l0r);
        pack_hilo(acc[nf][2] + b0, acc[nf][3] + b1, h1, l1r);
        u32 off0 = sw128((u32)(rl0 * 128 + nl * 2));
        u32 off1 = sw128((u32)(rl1 * 128 + nl * 2));
        *(u32*)(ph[sel] + off0) = h0;
        *(u32*)(pl[sel] + off0) = l0r;
        *(u32*)(ph[sel] + off1) = h1;
        *(u32*)(pl[sel] + off1) = l1r;
    }
}

// ============================ Attention kernel ============================
// CTA = (mt, b, s): 128 query rows, split-K half s of kt range. cp.async
// double-buffered pre-swizzled bf16 planes; no conversion in the loop.
// No-max softmax; partial O (fp32, unnormalized) + partial l to gmem.
#define ATQ_H 0
#define ATQ_L 16384
#define ATKV0 32768                 // per buf: KH, KL, VH, VL (16KB each)
#define AT_SMEM (32768 + 2 * 65536) // 163840

__device__ __forceinline__ void copy_kv(u32 dst, int b, int kt, int t) {
    size_t tb = ((size_t)(b * 32 + kt)) * TILE_BYTES;
    copy_plane(dst,          (const char*)g_kh + tb, t);
    copy_plane(dst + 16384,  (const char*)g_kl + tb, t);
    copy_plane(dst + 32768,  (const char*)g_vh + tb, t);
    copy_plane(dst + 49152,  (const char*)g_vl + tb, t);
}

__global__ __launch_bounds__(256) void attn_kernel()
{
    extern __shared__ char sm[];
    const u32 smb = smem_u32(sm);
    const int t = threadIdx.x, w = t >> 5, lane = t & 31;
    const int g = lane >> 2, tg = lane & 3;
    const int gb = blockIdx.x;
    const int mt = 31 - (gb >> 3);       // heavy tiles first
    const int b  = (gb >> 1) & 3;
    const int s  = gb & 1;
    const int mb = 16 * w;
    const float scale = 1.0f / 32.0f;

    const int n_t = mt + 1;
    const int h   = (n_t + 1) >> 1;
    const int kt0 = s ? h : 0;
    const int cnt = s ? (n_t - h) : h;

    if (cnt > 0) {
        size_t qb = ((size_t)(b * 32 + mt)) * TILE_BYTES;
        copy_plane(smb + ATQ_H, (const char*)g_qh + qb, t);
        copy_plane(smb + ATQ_L, (const char*)g_ql + qb, t);
        copy_kv(smb + ATKV0, b, kt0, t);
        cp_commit();
        if (cnt > 1) {
            copy_kv(smb + ATKV0 + 65536, b, kt0 + 1, t);
            cp_commit();
        }
    }

    u32 qH[4][4], qL[4][4];
    float oacc[8][4];
    #pragma unroll
    for (int i = 0; i < 8; i++)
        #pragma unroll
        for (int e = 0; e < 4; e++) oacc[i][e] = 0.0f;
    float l0 = 0.0f, l1 = 0.0f;
    const int rowg0 = mt * 128 + mb + g, rowg1 = rowg0 + 8;  // within batch

    for (int i = 0; i < cnt; i++) {
        if (i + 1 < cnt) asm volatile("cp.async.wait_group 1;" ::: "memory");
        else             asm volatile("cp.async.wait_group 0;" ::: "memory");
        __syncthreads();

        if (i == 0) {
            #pragma unroll
            for (int kk = 0; kk < 4; kk++) {
                ldsm4(frag_addr(smb + ATQ_H, mb, kk * 32), qH[kk][0], qH[kk][1], qH[kk][2], qH[kk][3]);
                ldsm4(frag_addr(smb + ATQ_L, mb, kk * 32), qL[kk][0], qL[kk][1], qL[kk][2], qL[kk][3]);
            }
        }
        const int kt = kt0 + i;
        const u32 kb = smb + ATKV0 + (u32)(i & 1) * 65536;

        // ---- S = Q K^T (3 combos) ----
        float sacc[16][4];
        #pragma unroll
        for (int q2 = 0; q2 < 16; q2++)
            #pragma unroll
            for (int e = 0; e < 4; e++) sacc[q2][e] = 0.0f;
        #pragma unroll
        for (int nb = 0; nb < 8; nb++) {
            #pragma unroll
            for (int kk = 0; kk < 4; kk++) {
                u32 bh0, bh1, bh2, bh3, bl0, bl1, bl2, bl3;
                ldsm4(frag_addr(kb, nb * 16, kk * 32), bh0, bh1, bh2, bh3);
                ldsm4(frag_addr(kb + 16384, nb * 16, kk * 32), bl0, bl1, bl2, bl3);
                mma16816(sacc[2*nb],   qH[kk][0], qH[kk][1], qH[kk][2], qH[kk][3], bh0, bh2);
                mma16816(sacc[2*nb],   qH[kk][0], qH[kk][1], qH[kk][2], qH[kk][3], bl0, bl2);
                mma16816(sacc[2*nb],   qL[kk][0], qL[kk][1], qL[kk][2], qL[kk][3], bh0, bh2);
                mma16816(sacc[2*nb+1], qH[kk][0], qH[kk][1], qH[kk][2], qH[kk][3], bh1, bh3);
                mma16816(sacc[2*nb+1], qH[kk][0], qH[kk][1], qH[kk][2], qH[kk][3], bl1, bl3);
                mma16816(sacc[2*nb+1], qL[kk][0], qL[kk][1], qL[kk][2], qL[kk][3], bh1, bh3);
            }
        }

        // ---- exp (no max); mask only on the diagonal tile ----
        if (kt == mt) {
            #pragma unroll
            for (int nf = 0; nf < 16; nf++) {
                int colb = kt * 128 + nf * 8 + 2 * tg;
                float p0 = (colb     <= rowg0) ? __expf(sacc[nf][0] * scale) : 0.0f;
                float p1 = (colb + 1 <= rowg0) ? __expf(sacc[nf][1] * scale) : 0.0f;
                float p2 = (colb     <= rowg1) ? __expf(sacc[nf][2] * scale) : 0.0f;
                float p3 = (colb + 1 <= rowg1) ? __expf(sacc[nf][3] * scale) : 0.0f;
                l0 += p0 + p1; l1 += p2 + p3;
                sacc[nf][0] = p0; sacc[nf][1] = p1; sacc[nf][2] = p2; sacc[nf][3] = p3;
            }
        } else {
            #pragma unroll
            for (int nf = 0; nf < 16; nf++) {
                float p0 = __expf(sacc[nf][0] * scale);
                float p1 = __expf(sacc[nf][1] * scale);
                float p2 = __expf(sacc[nf][2] * scale);
                float p3 = __expf(sacc[nf][3] * scale);
                l0 += p0 + p1; l1 += p2 + p3;
                sacc[nf][0] = p0; sacc[nf][1] = p1; sacc[nf][2] = p2; sacc[nf][3] = p3;
            }
        }

        // ---- O += P V (P hi/lo in regs; V via ldmatrix.trans) ----
        #pragma unroll
        for (int kk = 0; kk < 8; kk++) {
            u32 ah[4], al[4];
            pack_hilo(sacc[2*kk][0],   sacc[2*kk][1],   ah[0], al[0]);
            pack_hilo(sacc[2*kk][2],   sacc[2*kk][3],   ah[1], al[1]);
            pack_hilo(sacc[2*kk+1][0], sacc[2*kk+1][1], ah[2], al[2]);
            pack_hilo(sacc[2*kk+1][2], sacc[2*kk+1][3], ah[3], al[3]);
            #pragma unroll
            for (int nb = 0; nb < 4; nb++) {
                u32 vh0, vh1, vh2, vh3, vl0, vl1, vl2, vl3;
                ldsm4t(frag_addr(kb + 32768, kk * 16, nb * 32), vh0, vh1, vh2, vh3);
                ldsm4t(frag_addr(kb + 49152, kk * 16, nb * 32), vl0, vl1, vl2, vl3);
                mma16816(oacc[2*nb],   ah[0], ah[1], ah[2], ah[3], vh0, vh1);
                mma16816(oacc[2*nb],   ah[0], ah[1], ah[2], ah[3], vl0, vl1);
                mma16816(oacc[2*nb],   al[0], al[1], al[2], al[3], vh0, vh1);
                mma16816(oacc[2*nb+1], ah[0], ah[1], ah[2], ah[3], vh2, vh3);
                mma16816(oacc[2*nb+1], ah[0], ah[1], ah[2], ah[3], vl2, vl3);
                mma16816(oacc[2*nb+1], al[0], al[1], al[2], al[3], vh2, vh3);
            }
        }

        __syncthreads();
        if (i + 2 < cnt) {
            copy_kv(smb + ATKV0 + (u32)(i & 1) * 65536, b, kt + 2, t);
            cp_commit();
        }
    }

    // ---- epilogue: partial sums to gmem ----
    l0 += __shfl_xor_sync(0xffffffffu, l0, 1);
    l0 += __shfl_xor_sync(0xffffffffu, l0, 2);
    l1 += __shfl_xor_sync(0xffffffffu, l1, 1);
    l1 += __shfl_xor_sync(0xffffffffu, l1, 2);

    const size_t gr0 = (size_t)b * SEQ + rowg0;
    const size_t gr1 = gr0 + 8;
    float* po = g_po[s];
    #pragma unroll
    for (int nf = 0; nf < 8; nf++) {
        int col = nf * 8 + 2 * tg;
        *(float2*)&po[gr0 * HEAD + col] = make_float2(oacc[nf][0], oacc[nf][1]);
        *(float2*)&po[gr1 * HEAD + col] = make_float2(oacc[nf][2], oacc[nf][3]);
    }
    if (tg == 0) {
        g_pl[s][gr0] = l0;
        g_pl[s][gr1] = l1;
    }
}

// ============================ Combine kernel ============================
__global__ __launch_bounds__(256) void combine_kernel(float* __restrict__ out)
{
    int idx = blockIdx.x * 256 + threadIdx.x;     // over BT*HEAD/4 float4s
    float4 a = ((const float4*)g_po[0])[idx];
    float4 c = ((const float4*)g_po[1])[idx];
    int row = idx >> 4;
    float inv = 1.0f / (g_pl[0][row] + g_pl[1][row]);
    float4 r;
    r.x = (a.x + c.x) * inv;
    r.y = (a.y + c.y) * inv;
    r.z = (a.z + c.z) * inv;
    r.w = (a.w + c.w) * inv;
    ((float4*)out)[idx] = r;
}

// ============================ Launch ============================
extern "C" void kernel_launch(void* const* d_in, const int* in_sizes, int n_in,
                              void* d_out, int out_size)
{
    const float* x  = (const float*)d_in[0];
    const float* Wq = (const float*)d_in[1];
    const float* bq = (const float*)d_in[2];
    const float* Wk = (const float*)d_in[3];
    const float* bk = (const float*)d_in[4];
    const float* Wv = (const float*)d_in[5];
    const float* bv = (const float*)d_in[6];
    float* out = (float*)d_out;
    (void)in_sizes; (void)n_in; (void)out_size;

    cudaFuncSetAttribute(proj_kernel, cudaFuncAttributeMaxDynamicSharedMemorySize, PJ_SMEM);
    cudaFuncSetAttribute(attn_kernel, cudaFuncAttributeMaxDynamicSharedMemorySize, AT_SMEM);

    proj_kernel<<<BT / 128, 256, PJ_SMEM>>>(x, Wq, bq, Wk, bk, Wv, bv);
    attn_kernel<<<256, 256, AT_SMEM>>>();
    combine_kernel<<<BT * HEAD / 4 / 256, 256>>>(out);
}

// round 6
// speedup vs baseline: 8.3851x; 1.2083x over previous
#include <cuda_runtime.h>

#define BATCH   4
#define SEQ     4096
#define DMODEL  1024
#define HEAD    64
#define BT      (BATCH * SEQ)
#define TILE_BYTES 16384   // one 128x64 bf16 plane tile, SW128 swizzled

typedef unsigned int u32;
typedef unsigned short u16;

// bf16 hi/lo operand planes (attention-ready swizzled tile layout)
__device__ u16 g_qh[BT * HEAD];
__device__ u16 g_ql[BT * HEAD];
__device__ u16 g_kh[BT * HEAD];
__device__ u16 g_kl[BT * HEAD];
__device__ u16 g_vh[BT * HEAD];
__device__ u16 g_vl[BT * HEAD];
// W planes: tile (sel, chunk c) = 64 n-rows x 64 k, 8KB each, n-major SW128
__device__ u16 g_wh[3 * DMODEL * HEAD];
__device__ u16 g_wl[3 * DMODEL * HEAD];
// split-K partials
__device__ float g_po[2][BT * HEAD];
__device__ float g_pl[2][BT];

// ============================ helpers ============================
__device__ __forceinline__ u32 smem_u32(const void* p) {
    u32 a;
    asm("{ .reg .u64 t; cvta.to.shared.u64 t, %1; cvt.u32.u64 %0, t; }" : "=r"(a) : "l"(p));
    return a;
}
__device__ __forceinline__ u32 sw128(u32 off) { return off ^ ((off >> 3) & 0x70); }

__device__ __forceinline__ void ldsm4(u32 a, u32& r0, u32& r1, u32& r2, u32& r3) {
    asm volatile("ldmatrix.sync.aligned.m8n8.x4.shared.b16 {%0,%1,%2,%3}, [%4];"
                 : "=r"(r0), "=r"(r1), "=r"(r2), "=r"(r3) : "r"(a));
}
__device__ __forceinline__ void ldsm4t(u32 a, u32& r0, u32& r1, u32& r2, u32& r3) {
    asm volatile("ldmatrix.sync.aligned.m8n8.x4.trans.shared.b16 {%0,%1,%2,%3}, [%4];"
                 : "=r"(r0), "=r"(r1), "=r"(r2), "=r"(r3) : "r"(a));
}
__device__ __forceinline__ void mma16816(float* d, u32 a0, u32 a1, u32 a2, u32 a3,
                                         u32 b0, u32 b1) {
    asm volatile(
        "mma.sync.aligned.m16n8k16.row.col.f32.bf16.bf16.f32 "
        "{%0,%1,%2,%3},{%4,%5,%6,%7},{%8,%9},{%0,%1,%2,%3};"
        : "+f"(d[0]), "+f"(d[1]), "+f"(d[2]), "+f"(d[3])
        : "r"(a0), "r"(a1), "r"(a2), "r"(a3), "r"(b0), "r"(b1));
}
__device__ __forceinline__ void pack_hilo(float a, float b, u32& h, u32& l) {
    asm("cvt.rn.bf16x2.f32 %0, %1, %2;" : "=r"(h) : "f"(b), "f"(a));
    float ra = __uint_as_float(h << 16);
    float rb = __uint_as_float(h & 0xFFFF0000u);
    asm("cvt.rn.bf16x2.f32 %0, %1, %2;" : "=r"(l) : "f"(b - rb), "f"(a - ra));
}
__device__ __forceinline__ u32 frag_addr(u32 base, int row0, int colb) {
    int lane = threadIdx.x & 31;
    int tile = lane >> 3, l7 = lane & 7;
    int row = row0 + l7 + ((tile & 1) << 3);
    int col = colb + ((tile >> 1) << 4);
    return base + sw128((u32)(row * 128 + col));
}
__device__ __forceinline__ void cpa16(u32 dst, const void* src) {
    asm volatile("cp.async.cg.shared.global [%0], [%1], 16;" :: "r"(dst), "l"(src));
}
__device__ __forceinline__ void cp_commit() {
    asm volatile("cp.async.commit_group;" ::: "memory");
}
__device__ __forceinline__ void copy_plane(u32 dst, const char* src, int t) {
    #pragma unroll
    for (int j = 0; j < 4; j++)
        cpa16(dst + (u32)(t * 16 + j * 4096), src + t * 16 + j * 4096);
}

// ============================ W prepass ============================
// grid 48 = 3 sels x 16 chunks. Tile (sel,c): 64 n-rows x 128B (k*2), SW128.
__global__ __launch_bounds__(256) void wprep_kernel(
    const float* __restrict__ Wq, const float* __restrict__ Wk,
    const float* __restrict__ Wv)
{
    const int sel = blockIdx.x >> 4, c = blockIdx.x & 15;
    const float* W = (sel == 0) ? Wq : (sel == 1) ? Wk : Wv;
    const int k0 = c * 64;
    char* th = (char*)g_wh + (size_t)(sel * 16 + c) * 8192;
    char* tl = (char*)g_wl + (size_t)(sel * 16 + c) * 8192;
    const int t = threadIdx.x;
    #pragma unroll
    for (int j = 0; j < 8; j++) {
        int idx = t + j * 256;           // 2048 = 32 kq x 64 n
        int kq = idx >> 6, n = idx & 63;
        float w0 = W[(size_t)(k0 + 2 * kq)     * HEAD + n];
        float w1 = W[(size_t)(k0 + 2 * kq + 1) * HEAD + n];
        u32 h, l;
        pack_hilo(w0, w1, h, l);
        u32 off = sw128((u32)(n * 128 + kq * 4));
        *(u32*)(th + off) = h;
        *(u32*)(tl + off) = l;
    }
}

// ============================ Projection kernel ============================
// CTA: 128 rows of x, 192 output cols (q|k|v). cp.async double-buffered:
// stage = raw fp32 x chunk (32KB) + W plane tiles (48KB). x converted to bf16
// hi/lo in-CTA; W arrives pre-converted/pre-swizzled from wprep.
#define PX0   0
#define PW0   65536
#define PXH   163840
#define PXL   180224
#define PJ_SMEM 196608

__device__ __forceinline__ void pj_copy_stage(u32 smb, const float* x, int m0,
                                              int c, int t) {
    const u32 st = (u32)(c & 1);
    const u32 xd = smb + PX0 + st * 32768;
    const int k0 = c * 64;
    #pragma unroll
    for (int j = 0; j < 8; j++) {
        int i = t + j * 256;             // 2048 x 16B
        int r = i >> 4, cq = i & 15;
        cpa16(xd + (u32)(r * 256 + cq * 16),
              &x[(size_t)(m0 + r) * DMODEL + k0 + cq * 4]);
    }
    const u32 wd = smb + PW0 + st * 49152;
    #pragma unroll
    for (int sel = 0; sel < 3; sel++) {
        const char* sh = (const char*)g_wh + (size_t)(sel * 16 + c) * 8192;
        const char* sl = (const char*)g_wl + (size_t)(sel * 16 + c) * 8192;
        #pragma unroll
        for (int j = 0; j < 2; j++) {
            int i = t + j * 256;         // 512 x 16B = 8KB
            cpa16(wd + (u32)(sel * 8192 + i * 16), sh + i * 16);
            cpa16(wd + 24576u + (u32)(sel * 8192 + i * 16), sl + i * 16);
        }
    }
    cp_commit();
}

__global__ __launch_bounds__(256) void proj_kernel(
    const float* __restrict__ x,
    const float* __restrict__ bq, const float* __restrict__ bk,
    const float* __restrict__ bv)
{
    extern __shared__ char sm[];
    const u32 smb = smem_u32(sm);
    const int t = threadIdx.x, w = t >> 5, lane = t & 31;
    const int g = lane >> 2, tg = lane & 3;
    const int m0 = blockIdx.x * 128;
    const int mb = 16 * w;

    const float* Bs[3] = { bq, bk, bv };

    float acc[24][4];
    #pragma unroll
    for (int i = 0; i < 24; i++)
        #pragma unroll
        for (int e = 0; e < 4; e++) acc[i][e] = 0.0f;

    pj_copy_stage(smb, x, m0, 0, t);
    pj_copy_stage(smb, x, m0, 1, t);

    for (int c = 0; c < 16; c++) {
        if (c + 1 < 16) asm volatile("cp.async.wait_group 1;" ::: "memory");
        else            asm volatile("cp.async.wait_group 0;" ::: "memory");
        __syncthreads();

        const u32 st = (u32)(c & 1);
        const u32 xr = smb + PX0 + st * 32768;
        // convert x chunk fp32 -> bf16 hi/lo planes
        #pragma unroll
        for (int j = 0; j < 8; j++) {
            int idx = t + j * 256;
            int r = idx >> 4, cq = idx & 15;
            float4 v;
            asm volatile("ld.shared.v4.f32 {%0,%1,%2,%3}, [%4];"
                         : "=f"(v.x), "=f"(v.y), "=f"(v.z), "=f"(v.w)
                         : "r"(xr + (u32)(r * 256 + cq * 16)));
            uint2 h, l;
            pack_hilo(v.x, v.y, h.x, l.x);
            pack_hilo(v.z, v.w, h.y, l.y);
            u32 off = sw128((u32)(r * 128 + cq * 8));
            *(uint2*)(sm + PXH + off) = h;
            *(uint2*)(sm + PXL + off) = l;
        }
        __syncthreads();

        u32 aH[4][4], aL[4][4];
        #pragma unroll
        for (int kk = 0; kk < 4; kk++) {
            ldsm4(frag_addr(smb + PXH, mb, kk * 32), aH[kk][0], aH[kk][1], aH[kk][2], aH[kk][3]);
            ldsm4(frag_addr(smb + PXL, mb, kk * 32), aL[kk][0], aL[kk][1], aL[kk][2], aL[kk][3]);
        }
        const u32 wb = smb + PW0 + st * 49152;
        #pragma unroll
        for (int sel = 0; sel < 3; sel++) {
            const u32 whb = wb + (u32)(sel * 8192);
            const u32 wlb = whb + 24576u;
            #pragma unroll
            for (int nb = 0; nb < 4; nb++) {
                float* a0 = acc[sel * 8 + 2 * nb];
                float* a1 = acc[sel * 8 + 2 * nb + 1];
                #pragma unroll
                for (int kk = 0; kk < 4; kk++) {
                    u32 bh0, bh1, bh2, bh3, bl0, bl1, bl2, bl3;
                    ldsm4(frag_addr(whb, nb * 16, kk * 32), bh0, bh1, bh2, bh3);
                    ldsm4(frag_addr(wlb, nb * 16, kk * 32), bl0, bl1, bl2, bl3);
                    mma16816(a0, aH[kk][0], aH[kk][1], aH[kk][2], aH[kk][3], bh0, bh2);
                    mma16816(a0, aH[kk][0], aH[kk][1], aH[kk][2], aH[kk][3], bl0, bl2);
                    mma16816(a0, aL[kk][0], aL[kk][1], aL[kk][2], aL[kk][3], bh0, bh2);
                    mma16816(a1, aH[kk][0], aH[kk][1], aH[kk][2], aH[kk][3], bh1, bh3);
                    mma16816(a1, aH[kk][0], aH[kk][1], aH[kk][2], aH[kk][3], bl1, bl3);
                    mma16816(a1, aL[kk][0], aL[kk][1], aL[kk][2], aL[kk][3], bh1, bh3);
                }
            }
        }
        __syncthreads();
        if (c + 2 < 16) pj_copy_stage(smb, x, m0, c + 2, t);
    }

    // epilogue: bias, bf16 hi/lo split, write swizzled tile planes
    const size_t pbase = (size_t)blockIdx.x * TILE_BYTES;
    char* ph[3] = { (char*)g_qh + pbase, (char*)g_kh + pbase, (char*)g_vh + pbase };
    char* pl[3] = { (char*)g_ql + pbase, (char*)g_kl + pbase, (char*)g_vl + pbase };
    const int rl0 = mb + g, rl1 = rl0 + 8;
    #pragma unroll
    for (int nf = 0; nf < 24; nf++) {
        int n = nf * 8 + 2 * tg;
        int sel = n >> 6, nl = n & 63;
        float b0 = Bs[sel][nl], b1 = Bs[sel][nl + 1];
        u32 h0, l0r, h1, l1r;
        pack_hilo(acc[nf][0] + b0, acc[nf][1] + b1, h0, l0r);
        pack_hilo(acc[nf][2] + b0, acc[nf][3] + b1, h1, l1r);
        u32 off0 = sw128((u32)(rl0 * 128 + nl * 2));
        u32 off1 = sw128((u32)(rl1 * 128 + nl * 2));
        *(u32*)(ph[sel] + off0) = h0;
        *(u32*)(pl[sel] + off0) = l0r;
        *(u32*)(ph[sel] + off1) = h1;
        *(u32*)(pl[sel] + off1) = l1r;
    }
}

// ============================ Attention kernel ============================
#define ATQ_H 0
#define ATQ_L 16384
#define ATKV0 32768
#define AT_SMEM (32768 + 2 * 65536)

__device__ __forceinline__ void copy_kv(u32 dst, int b, int kt, int t) {
    size_t tb = ((size_t)(b * 32 + kt)) * TILE_BYTES;
    copy_plane(dst,          (const char*)g_kh + tb, t);
    copy_plane(dst + 16384,  (const char*)g_kl + tb, t);
    copy_plane(dst + 32768,  (const char*)g_vh + tb, t);
    copy_plane(dst + 49152,  (const char*)g_vl + tb, t);
}

__global__ __launch_bounds__(256) void attn_kernel()
{
    extern __shared__ char sm[];
    const u32 smb = smem_u32(sm);
    const int t = threadIdx.x, w = t >> 5, lane = t & 31;
    const int g = lane >> 2, tg = lane & 3;
    const int gb = blockIdx.x;
    const int mt = 31 - (gb >> 3);
    const int b  = (gb >> 1) & 3;
    const int s  = gb & 1;
    const int mb = 16 * w;
    const float scale = 1.0f / 32.0f;

    const int n_t = mt + 1;
    const int h   = (n_t + 1) >> 1;
    const int kt0 = s ? h : 0;
    const int cnt = s ? (n_t - h) : h;

    if (cnt > 0) {
        size_t qb = ((size_t)(b * 32 + mt)) * TILE_BYTES;
        copy_plane(smb + ATQ_H, (const char*)g_qh + qb, t);
        copy_plane(smb + ATQ_L, (const char*)g_ql + qb, t);
        copy_kv(smb + ATKV0, b, kt0, t);
        cp_commit();
        if (cnt > 1) {
            copy_kv(smb + ATKV0 + 65536, b, kt0 + 1, t);
            cp_commit();
        }
    }

    u32 qH[4][4], qL[4][4];
    float oacc[8][4];
    #pragma unroll
    for (int i = 0; i < 8; i++)
        #pragma unroll
        for (int e = 0; e < 4; e++) oacc[i][e] = 0.0f;
    float l0 = 0.0f, l1 = 0.0f;
    const int rowg0 = mt * 128 + mb + g, rowg1 = rowg0 + 8;

    for (int i = 0; i < cnt; i++) {
        if (i + 1 < cnt) asm volatile("cp.async.wait_group 1;" ::: "memory");
        else             asm volatile("cp.async.wait_group 0;" ::: "memory");
        __syncthreads();

        if (i == 0) {
            #pragma unroll
            for (int kk = 0; kk < 4; kk++) {
                ldsm4(frag_addr(smb + ATQ_H, mb, kk * 32), qH[kk][0], qH[kk][1], qH[kk][2], qH[kk][3]);
                ldsm4(frag_addr(smb + ATQ_L, mb, kk * 32), qL[kk][0], qL[kk][1], qL[kk][2], qL[kk][3]);
            }
        }
        const int kt = kt0 + i;
        const u32 kb = smb + ATKV0 + (u32)(i & 1) * 65536;

        float sacc[16][4];
        #pragma unroll
        for (int q2 = 0; q2 < 16; q2++)
            #pragma unroll
            for (int e = 0; e < 4; e++) sacc[q2][e] = 0.0f;
        #pragma unroll
        for (int nb = 0; nb < 8; nb++) {
            #pragma unroll
            for (int kk = 0; kk < 4; kk++) {
                u32 bh0, bh1, bh2, bh3, bl0, bl1, bl2, bl3;
                ldsm4(frag_addr(kb, nb * 16, kk * 32), bh0, bh1, bh2, bh3);
                ldsm4(frag_addr(kb + 16384, nb * 16, kk * 32), bl0, bl1, bl2, bl3);
                mma16816(sacc[2*nb],   qH[kk][0], qH[kk][1], qH[kk][2], qH[kk][3], bh0, bh2);
                mma16816(sacc[2*nb],   qH[kk][0], qH[kk][1], qH[kk][2], qH[kk][3], bl0, bl2);
                mma16816(sacc[2*nb],   qL[kk][0], qL[kk][1], qL[kk][2], qL[kk][3], bh0, bh2);
                mma16816(sacc[2*nb+1], qH[kk][0], qH[kk][1], qH[kk][2], qH[kk][3], bh1, bh3);
                mma16816(sacc[2*nb+1], qH[kk][0], qH[kk][1], qH[kk][2], qH[kk][3], bl1, bl3);
                mma16816(sacc[2*nb+1], qL[kk][0], qL[kk][1], qL[kk][2], qL[kk][3], bh1, bh3);
            }
        }

        if (kt == mt) {
            #pragma unroll
            for (int nf = 0; nf < 16; nf++) {
                int colb = kt * 128 + nf * 8 + 2 * tg;
                float p0 = (colb     <= rowg0) ? __expf(sacc[nf][0] * scale) : 0.0f;
                float p1 = (colb + 1 <= rowg0) ? __expf(sacc[nf][1] * scale) : 0.0f;
                float p2 = (colb     <= rowg1) ? __expf(sacc[nf][2] * scale) : 0.0f;
                float p3 = (colb + 1 <= rowg1) ? __expf(sacc[nf][3] * scale) : 0.0f;
                l0 += p0 + p1; l1 += p2 + p3;
                sacc[nf][0] = p0; sacc[nf][1] = p1; sacc[nf][2] = p2; sacc[nf][3] = p3;
            }
        } else {
            #pragma unroll
            for (int nf = 0; nf < 16; nf++) {
                float p0 = __expf(sacc[nf][0] * scale);
                float p1 = __expf(sacc[nf][1] * scale);
                float p2 = __expf(sacc[nf][2] * scale);
                float p3 = __expf(sacc[nf][3] * scale);
                l0 += p0 + p1; l1 += p2 + p3;
                sacc[nf][0] = p0; sacc[nf][1] = p1; sacc[nf][2] = p2; sacc[nf][3] = p3;
            }
        }

        #pragma unroll
        for (int kk = 0; kk < 8; kk++) {
            u32 ah[4], al[4];
            pack_hilo(sacc[2*kk][0],   sacc[2*kk][1],   ah[0], al[0]);
            pack_hilo(sacc[2*kk][2],   sacc[2*kk][3],   ah[1], al[1]);
            pack_hilo(sacc[2*kk+1][0], sacc[2*kk+1][1], ah[2], al[2]);
            pack_hilo(sacc[2*kk+1][2], sacc[2*kk+1][3], ah[3], al[3]);
            #pragma unroll
            for (int nb = 0; nb < 4; nb++) {
                u32 vh0, vh1, vh2, vh3, vl0, vl1, vl2, vl3;
                ldsm4t(frag_addr(kb + 32768, kk * 16, nb * 32), vh0, vh1, vh2, vh3);
                ldsm4t(frag_addr(kb + 49152, kk * 16, nb * 32), vl0, vl1, vl2, vl3);
                mma16816(oacc[2*nb],   ah[0], ah[1], ah[2], ah[3], vh0, vh1);
                mma16816(oacc[2*nb],   ah[0], ah[1], ah[2], ah[3], vl0, vl1);
                mma16816(oacc[2*nb],   al[0], al[1], al[2], al[3], vh0, vh1);
                mma16816(oacc[2*nb+1], ah[0], ah[1], ah[2], ah[3], vh2, vh3);
                mma16816(oacc[2*nb+1], ah[0], ah[1], ah[2], ah[3], vl2, vl3);
                mma16816(oacc[2*nb+1], al[0], al[1], al[2], al[3], vh2, vh3);
            }
        }

        __syncthreads();
        if (i + 2 < cnt) {
            copy_kv(smb + ATKV0 + (u32)(i & 1) * 65536, b, kt + 2, t);
            cp_commit();
        }
    }

    l0 += __shfl_xor_sync(0xffffffffu, l0, 1);
    l0 += __shfl_xor_sync(0xffffffffu, l0, 2);
    l1 += __shfl_xor_sync(0xffffffffu, l1, 1);
    l1 += __shfl_xor_sync(0xffffffffu, l1, 2);

    const size_t gr0 = (size_t)b * SEQ + rowg0;
    const size_t gr1 = gr0 + 8;
    float* po = g_po[s];
    #pragma unroll
    for (int nf = 0; nf < 8; nf++) {
        int col = nf * 8 + 2 * tg;
        *(float2*)&po[gr0 * HEAD + col] = make_float2(oacc[nf][0], oacc[nf][1]);
        *(float2*)&po[gr1 * HEAD + col] = make_float2(oacc[nf][2], oacc[nf][3]);
    }
    if (tg == 0) {
        g_pl[s][gr0] = l0;
        g_pl[s][gr1] = l1;
    }
}

// ============================ Combine kernel ============================
__global__ __launch_bounds__(256) void combine_kernel(float* __restrict__ out)
{
    int idx = blockIdx.x * 256 + threadIdx.x;
    float4 a = ((const float4*)g_po[0])[idx];
    float4 c = ((const float4*)g_po[1])[idx];
    int row = idx >> 4;
    float inv = 1.0f / (g_pl[0][row] + g_pl[1][row]);
    float4 r;
    r.x = (a.x + c.x) * inv;
    r.y = (a.y + c.y) * inv;
    r.z = (a.z + c.z) * inv;
    r.w = (a.w + c.w) * inv;
    ((float4*)out)[idx] = r;
}

// ============================ Launch ============================
extern "C" void kernel_launch(void* const* d_in, const int* in_sizes, int n_in,
                              void* d_out, int out_size)
{
    const float* x  = (const float*)d_in[0];
    const float* Wq = (const float*)d_in[1];
    const float* bq = (const float*)d_in[2];
    const float* Wk = (const float*)d_in[3];
    const float* bk = (const float*)d_in[4];
    const float* Wv = (const float*)d_in[5];
    const float* bv = (const float*)d_in[6];
    float* out = (float*)d_out;
    (void)in_sizes; (void)n_in; (void)out_size;

    cudaFuncSetAttribute(proj_kernel, cudaFuncAttributeMaxDynamicSharedMemorySize, PJ_SMEM);
    cudaFuncSetAttribute(attn_kernel, cudaFuncAttributeMaxDynamicSharedMemorySize, AT_SMEM);

    wprep_kernel<<<48, 256>>>(Wq, Wk, Wv);
    proj_kernel<<<BT / 128, 256, PJ_SMEM>>>(x, bq, bk, bv);
    attn_kernel<<<256, 256, AT_SMEM>>>();
    combine_kernel<<<BT * HEAD / 4 / 256, 256>>>(out);
}